// round 5
// baseline (speedup 1.0000x reference)
#include <cuda_runtime.h>
#include <math.h>

// Problem-scale upper bounds (N=50000, Etot=850000)
#define MAXN 50176
#define MAXE 1048576

// ---------------- scratch (device globals, referenced directly) ----------------
__device__ float g_hA[MAXN * 64];
__device__ float g_hB[MAXN * 64];
__device__ float g_fA[MAXN * 64];
__device__ float g_fB[MAXN * 64];
__device__ float g_as[MAXN];
__device__ float g_ad[MAXN];
__device__ int   g_deg[MAXN];
__device__ int   g_offs[MAXN + 1];
__device__ int   g_cursor[MAXN];
__device__ int   g_csr_src[MAXE];
__device__ int   g_csr_eid[MAXE];

// buffer id -> device pointer (resolved in device code; no host symbol queries)
__device__ __forceinline__ float* buf_ptr(int id) {
    switch (id) {
        case 0:  return g_hA;
        case 1:  return g_hB;
        case 2:  return g_fA;
        default: return g_fB;
    }
}

// ---------------- CSR build kernels (edge_index is int32!) ----------------
__global__ void zero_deg_kernel(int N) {
    int i = blockIdx.x * blockDim.x + threadIdx.x;
    if (i < N) g_deg[i] = 0;
}

__global__ void build_deg_kernel(const int* __restrict__ ei, int E, int N) {
    int e = blockIdx.x * blockDim.x + threadIdx.x;
    int Etot = E + N;
    if (e >= Etot) return;
    int d = (e < E) ? ei[E + e] : (e - E);
    atomicAdd(&g_deg[d], 1);
}

// single-block exclusive scan over N entries -> g_offs[0..N], g_cursor copy
__global__ void scan_kernel(int N) {
    __shared__ int sm[1024];
    __shared__ int carry;
    int tid = threadIdx.x;
    if (tid == 0) carry = 0;
    __syncthreads();
    for (int base = 0; base < N; base += 1024) {
        int i = base + tid;
        int v = (i < N) ? g_deg[i] : 0;
        sm[tid] = v;
        __syncthreads();
        #pragma unroll
        for (int off = 1; off < 1024; off <<= 1) {
            int t = (tid >= off) ? sm[tid - off] : 0;
            __syncthreads();
            sm[tid] += t;
            __syncthreads();
        }
        int exc = sm[tid] - v;
        if (i < N) { g_offs[i] = carry + exc; g_cursor[i] = carry + exc; }
        __syncthreads();
        if (tid == 0) carry += sm[1023];
        __syncthreads();
    }
    if (tid == 0) g_offs[N] = carry;
}

__global__ void scatter_kernel(const int* __restrict__ ei, int E, int N) {
    int e = blockIdx.x * blockDim.x + threadIdx.x;
    int Etot = E + N;
    if (e >= Etot) return;
    int s, d;
    if (e < E) { s = ei[e]; d = ei[E + e]; }
    else       { s = e - E; d = e - E; }
    int pos = atomicAdd(&g_cursor[d], 1);
    g_csr_src[pos] = s;
    g_csr_eid[pos] = e;
}

// write stacked [src; dst] (with self loops) as float into the output head
__global__ void srcdst_kernel(const int* __restrict__ ei, int E, int N,
                              float* __restrict__ out) {
    int e = blockIdx.x * blockDim.x + threadIdx.x;
    int Etot = E + N;
    if (e >= Etot) return;
    int s, d;
    if (e < E) { s = ei[e]; d = ei[E + e]; }
    else       { s = d = e - E; }
    out[e]        = (float)s;
    out[Etot + e] = (float)d;
}

// ---------------- dense GEMM: H[N,FOUT] = X[N,FIN] @ W[FOUT,FIN]^T ----------------
// 256 threads as 16x16, tile = 64 nodes x FOUT feats, register tile 4 x (FOUT/16).
template <int FIN, int FOUT>
__global__ void gemm_kernel(const float* __restrict__ xptr, int xbuf,
                            const float* __restrict__ W, int hbuf, int N) {
    const float* X = xptr ? xptr : buf_ptr(xbuf);
    float* H = buf_ptr(hbuf);

    constexpr int FPT = FOUT / 16;   // feats per thread (4 or 2)
    constexpr int KC  = 64;          // k chunk
    constexpr int XS  = KC + 1;
    constexpr int WS  = FOUT + 1;
    __shared__ float Xs[64 * XS];
    __shared__ float Ws[KC * WS];

    int tid   = threadIdx.x;
    int nbase = blockIdx.x * 64;
    int tx = tid & 15, ty = tid >> 4;
    int f0 = tx * FPT;

    float acc[4][FPT];
    #pragma unroll
    for (int i = 0; i < 4; i++)
        #pragma unroll
        for (int j = 0; j < FPT; j++) acc[i][j] = 0.f;

    for (int kc = 0; kc < FIN; kc += KC) {
        for (int t = tid; t < FOUT * KC; t += 256) {
            int f = t / KC, k = t % KC;
            Ws[k * WS + f] = W[f * FIN + kc + k];
        }
        for (int t = tid; t < 64 * KC; t += 256) {
            int n = t / KC, k = t % KC;
            int gn = nbase + n;
            Xs[n * XS + k] = (gn < N) ? X[gn * FIN + kc + k] : 0.f;
        }
        __syncthreads();
        #pragma unroll 4
        for (int k = 0; k < KC; k++) {
            float xv[4];
            #pragma unroll
            for (int i = 0; i < 4; i++) xv[i] = Xs[(ty * 4 + i) * XS + k];
            #pragma unroll
            for (int j = 0; j < FPT; j++) {
                float wv = Ws[k * WS + f0 + j];
                #pragma unroll
                for (int i = 0; i < 4; i++) acc[i][j] = fmaf(xv[i], wv, acc[i][j]);
            }
        }
        __syncthreads();
    }
    #pragma unroll
    for (int i = 0; i < 4; i++) {
        int gn = nbase + ty * 4 + i;
        if (gn < N) {
            #pragma unroll
            for (int j = 0; j < FPT; j++) H[gn * FOUT + f0 + j] = acc[i][j];
        }
    }
}

// per-node attention scores: g_as[n] = h[n,:]·a_src, g_ad[n] = h[n,:]·a_dst
__global__ void alpha_kernel(int hbuf, const float* __restrict__ a_s,
                             const float* __restrict__ a_d, int N, int F) {
    const float* h = buf_ptr(hbuf);
    int warp = (blockIdx.x * blockDim.x + threadIdx.x) >> 5;
    int lane = threadIdx.x & 31;
    if (warp >= N) return;
    float ps = 0.f, pd = 0.f;
    for (int f = lane; f < F; f += 32) {
        float hv = h[warp * F + f];
        ps = fmaf(hv, a_s[f], ps);
        pd = fmaf(hv, a_d[f], pd);
    }
    #pragma unroll
    for (int o = 16; o; o >>= 1) {
        ps += __shfl_xor_sync(0xffffffffu, ps, o);
        pd += __shfl_xor_sync(0xffffffffu, pd, o);
    }
    if (lane == 0) { g_as[warp] = ps; g_ad[warp] = pd; }
}

// ---------------- edge stage: warp per destination node ----------------
template <int F>
__global__ void edge_kernel(int hbuf, const float* __restrict__ bias,
                            float* __restrict__ optr, int obuf,
                            float* __restrict__ alpha_out, int N, int do_relu) {
    const float* h = buf_ptr(hbuf);
    float* out = optr ? optr : buf_ptr(obuf);

    int warp = (blockIdx.x * blockDim.x + threadIdx.x) >> 5;
    int lane = threadIdx.x & 31;
    if (warp >= N) return;
    int n   = warp;
    int beg = g_offs[n], end = g_offs[n + 1];
    float adv = g_ad[n];

    // pass 1: online softmax (running max + rescaled sum), lanes over edges
    float m = -1e30f, ssum = 0.f;
    for (int j = beg + lane; j < end; j += 32) {
        int s = g_csr_src[j];
        float e = g_as[s] + adv;
        e = (e > 0.f) ? e : 0.2f * e;
        float nm = fmaxf(m, e);
        ssum = ssum * __expf(m - nm) + __expf(e - nm);
        m = nm;
    }
    // warp merge of (m, ssum) pairs
    #pragma unroll
    for (int o = 16; o; o >>= 1) {
        float mo = __shfl_xor_sync(0xffffffffu, m, o);
        float so = __shfl_xor_sync(0xffffffffu, ssum, o);
        float nm = fmaxf(m, mo);
        ssum = ssum * __expf(m - nm) + so * __expf(mo - nm);
        m = nm;
    }
    float inv = 1.f / (ssum + 1e-16f);

    // pass 2: weighted gather-accumulate (edges serial, lanes over features)
    float acc0 = 0.f, acc1 = 0.f;
    for (int j = beg; j < end; j++) {
        int s = g_csr_src[j];                  // broadcast load
        float e = g_as[s] + adv;
        e = (e > 0.f) ? e : 0.2f * e;
        float ex = __expf(e - m);
        acc0 = fmaf(ex, h[s * F + lane], acc0);
        if (F == 64) acc1 = fmaf(ex, h[s * F + 32 + lane], acc1);
        if (alpha_out != nullptr && lane == 0) alpha_out[g_csr_eid[j]] = ex * inv;
    }
    float o0 = fmaf(acc0, inv, bias[lane]);
    if (do_relu) o0 = fmaxf(o0, 0.f);
    out[n * F + lane] = o0;
    if (F == 64) {
        float o1 = fmaf(acc1, inv, bias[32 + lane]);
        if (do_relu) o1 = fmaxf(o1, 0.f);
        out[n * F + 32 + lane] = o1;
    }
}

// ---------------- launch ----------------
extern "C" void kernel_launch(void* const* d_in, const int* in_sizes, int n_in,
                              void* d_out, int out_size) {
    const float* x  = (const float*)d_in[0];
    const int*   ei = (const int*)d_in[1];       // int32 (JAX x64 disabled)
    const float* W1 = (const float*)d_in[2];
    const float* as1 = (const float*)d_in[3];
    const float* ad1 = (const float*)d_in[4];
    const float* b1 = (const float*)d_in[5];
    const float* W2 = (const float*)d_in[6];
    const float* as2 = (const float*)d_in[7];
    const float* ad2 = (const float*)d_in[8];
    const float* b2 = (const float*)d_in[9];
    const float* W3 = (const float*)d_in[10];
    const float* as3 = (const float*)d_in[11];
    const float* ad3 = (const float*)d_in[12];
    const float* b3 = (const float*)d_in[13];

    int H1   = in_sizes[3];
    int FIN  = in_sizes[2] / H1;
    int N    = in_sizes[0] / FIN;
    int E    = in_sizes[1] / 2;
    int Etot = E + N;

    float* out = (float*)d_out;
    float* out_alpha = out + 2 * (size_t)Etot;
    float* out_feat  = out + 3 * (size_t)Etot;

    const int TB = 256;
    int ebl = (Etot + TB - 1) / TB;
    int nbl = (N + TB - 1) / TB;

    // ---- CSR build (shared by all 3 layers) ----
    zero_deg_kernel<<<nbl, TB>>>(N);
    build_deg_kernel<<<ebl, TB>>>(ei, E, N);
    scan_kernel<<<1, 1024>>>(N);
    scatter_kernel<<<ebl, TB>>>(ei, E, N);
    srcdst_kernel<<<ebl, TB>>>(ei, E, N, out);

    int gemm_bl = (N + 63) / 64;
    int warp_bl = (N * 32 + TB - 1) / TB;  // warp-per-node kernels

    // buffer ids: 0=g_hA, 1=g_hB, 2=g_fA, 3=g_fB
    // ---- layer 1: x[N,128] -> h in hA; feat out -> fA; alpha written ----
    gemm_kernel<128, 64><<<gemm_bl, 256>>>(x, -1, W1, 0, N);
    alpha_kernel<<<warp_bl, TB>>>(0, as1, ad1, N, 64);
    edge_kernel<64><<<warp_bl, TB>>>(0, b1, nullptr, 2, out_alpha, N, 1);

    // ---- layer 2: fA -> h in hB; feat out -> fB ----
    gemm_kernel<64, 64><<<gemm_bl, 256>>>(nullptr, 2, W2, 1, N);
    alpha_kernel<<<warp_bl, TB>>>(1, as2, ad2, N, 64);
    edge_kernel<64><<<warp_bl, TB>>>(1, b2, nullptr, 3, nullptr, N, 1);

    // ---- layer 3: fB -> h in hA (reuse); feat out -> out_feat (no relu) ----
    gemm_kernel<64, 32><<<gemm_bl, 256>>>(nullptr, 3, W3, 0, N);
    alpha_kernel<<<warp_bl, TB>>>(0, as3, ad3, N, 32);
    edge_kernel<32><<<warp_bl, TB>>>(0, b3, out_feat, -1, nullptr, N, 0);

    (void)n_in; (void)out_size;
}

// round 8
// speedup vs baseline: 1.1555x; 1.1555x over previous
#include <cuda_runtime.h>
#include <math.h>

// Problem-scale upper bounds (N=50000, Etot=850000)
#define MAXN 50176
#define MAXE 1048576

// ---------------- scratch (device globals, referenced directly) ----------------
__device__ float g_hA[MAXN * 64];
__device__ float g_hB[MAXN * 64];
__device__ float g_fA[MAXN * 64];
__device__ float g_fB[MAXN * 64];
__device__ float g_as[MAXN];
__device__ float g_ad[MAXN];
__device__ int   g_deg[MAXN];
__device__ int   g_offs[MAXN + 1];
__device__ int   g_cursor[MAXN];
__device__ int   g_csr_src[MAXE];
__device__ int   g_csr_eid[MAXE];

__device__ __forceinline__ float* buf_ptr(int id) {
    switch (id) {
        case 0:  return g_hA;
        case 1:  return g_hB;
        case 2:  return g_fA;
        default: return g_fB;
    }
}

// ---------------- CSR build ----------------
__global__ void zero_deg_kernel(int N) {
    int i = blockIdx.x * blockDim.x + threadIdx.x;
    if (i < N) g_deg[i] = 0;
}

// fused: degree histogram + write stacked [src;dst] floats to output head
__global__ void deg_srcdst_kernel(const int* __restrict__ ei, int E, int N,
                                  float* __restrict__ out) {
    int e = blockIdx.x * blockDim.x + threadIdx.x;
    int Etot = E + N;
    if (e >= Etot) return;
    int s, d;
    if (e < E) { s = ei[e]; d = ei[E + e]; }
    else       { s = d = e - E; }
    out[e]        = (float)s;
    out[Etot + e] = (float)d;
    atomicAdd(&g_deg[d], 1);
}

// single block, 1024 threads: each thread scans a contiguous chunk; block-scan of sums
__global__ void scan_kernel(int N) {
    __shared__ float dummy_pad[1];      // (unused)
    __shared__ int wsum[32];
    int tid  = threadIdx.x;
    int lane = tid & 31, wid = tid >> 5;
    int C = (N + 1023) / 1024;
    int lo = tid * C, hi = min(lo + C, N);

    int local = 0;
    for (int i = lo; i < hi; i++) local += g_deg[i];

    // warp inclusive scan of local
    int inc = local;
    #pragma unroll
    for (int o = 1; o < 32; o <<= 1) {
        int v = __shfl_up_sync(0xffffffffu, inc, o);
        if (lane >= o) inc += v;
    }
    if (lane == 31) wsum[wid] = inc;
    __syncthreads();
    if (wid == 0) {
        int w = (lane < 32) ? wsum[lane] : 0;
        #pragma unroll
        for (int o = 1; o < 32; o <<= 1) {
            int v = __shfl_up_sync(0xffffffffu, w, o);
            if (lane >= o) w += v;
        }
        wsum[lane] = w;
    }
    __syncthreads();
    int warp_excl = (wid == 0) ? 0 : wsum[wid - 1];
    int excl = warp_excl + inc - local;   // exclusive prefix for this thread's chunk

    int run = excl;
    for (int i = lo; i < hi; i++) {
        int v = g_deg[i];
        g_offs[i] = run;
        g_cursor[i] = run;
        run += v;
    }
    if (tid == 1023) g_offs[N] = run;
    (void)dummy_pad;
}

__global__ void scatter_kernel(const int* __restrict__ ei, int E, int N) {
    int e = blockIdx.x * blockDim.x + threadIdx.x;
    int Etot = E + N;
    if (e >= Etot) return;
    int s, d;
    if (e < E) { s = ei[e]; d = ei[E + e]; }
    else       { s = e - E; d = e - E; }
    int pos = atomicAdd(&g_cursor[d], 1);
    g_csr_src[pos] = s;
    g_csr_eid[pos] = e;
}

// ---------------- dense GEMM: H[N,FOUT] = X[N,FIN] @ W[FOUT,FIN]^T ----------------
// 256 threads (16x16). Tile = 128 nodes x FOUT. Per-thread 8 nodes x FPT feats.
// Xs stored k-major [KC][128] pitch 132, Ws k-major [KC][FOUT] pitch FOUT+4.
template <int FIN, int FOUT>
__global__ void gemm_kernel(const float* __restrict__ xptr, int xbuf,
                            const float* __restrict__ W, int hbuf, int N) {
    const float* X = xptr ? xptr : buf_ptr(xbuf);
    float* H = buf_ptr(hbuf);

    constexpr int FPT = FOUT / 16;     // 4 or 2
    constexpr int KC  = 32;
    constexpr int XP  = 132;           // pitch (floats), 16B-aligned rows
    constexpr int WP  = FOUT + 4;
    __shared__ float Xs[KC * XP];
    __shared__ float Ws[KC * WP];

    int tid   = threadIdx.x;
    int nbase = blockIdx.x * 128;
    int tx = tid & 15, ty = tid >> 4;
    int f0 = tx * FPT;
    int n0 = ty * 8;

    float acc[8][FPT];
    #pragma unroll
    for (int i = 0; i < 8; i++)
        #pragma unroll
        for (int j = 0; j < FPT; j++) acc[i][j] = 0.f;

    for (int kc = 0; kc < FIN; kc += KC) {
        // stage X: read coalesced along fin, write transposed
        #pragma unroll
        for (int t = tid; t < 128 * KC; t += 256) {
            int n = t / KC, k = t % KC;
            int gn = nbase + n;
            Xs[k * XP + n] = (gn < N) ? X[gn * FIN + kc + k] : 0.f;
        }
        // stage W: read coalesced along fin, write transposed
        for (int t = tid; t < FOUT * KC; t += 256) {
            int f = t / KC, k = t % KC;
            Ws[k * WP + f] = W[f * FIN + kc + k];
        }
        __syncthreads();
        #pragma unroll
        for (int k = 0; k < KC; k++) {
            float4 xa = *(const float4*)&Xs[k * XP + n0];
            float4 xb = *(const float4*)&Xs[k * XP + n0 + 4];
            float xv[8] = {xa.x, xa.y, xa.z, xa.w, xb.x, xb.y, xb.z, xb.w};
            float wv[FPT];
            if (FPT == 4) {
                float4 w4 = *(const float4*)&Ws[k * WP + f0];
                wv[0] = w4.x; wv[1] = w4.y; wv[2] = w4.z; wv[3] = w4.w;
            } else {
                float2 w2 = *(const float2*)&Ws[k * WP + f0];
                wv[0] = w2.x; wv[1] = w2.y;
            }
            #pragma unroll
            for (int i = 0; i < 8; i++)
                #pragma unroll
                for (int j = 0; j < FPT; j++)
                    acc[i][j] = fmaf(xv[i], wv[j], acc[i][j]);
        }
        __syncthreads();
    }
    #pragma unroll
    for (int i = 0; i < 8; i++) {
        int gn = nbase + n0 + i;
        if (gn < N) {
            #pragma unroll
            for (int j = 0; j < FPT; j++) H[gn * FOUT + f0 + j] = acc[i][j];
        }
    }
}

// per-node attention scores: g_as[n] = h[n,:]·a_src, g_ad[n] = h[n,:]·a_dst
__global__ void alpha_kernel(int hbuf, const float* __restrict__ a_s,
                             const float* __restrict__ a_d, int N, int F) {
    const float* h = buf_ptr(hbuf);
    int warp = (blockIdx.x * blockDim.x + threadIdx.x) >> 5;
    int lane = threadIdx.x & 31;
    if (warp >= N) return;
    float ps = 0.f, pd = 0.f;
    for (int f = lane; f < F; f += 32) {
        float hv = h[warp * F + f];
        ps = fmaf(hv, a_s[f], ps);
        pd = fmaf(hv, a_d[f], pd);
    }
    #pragma unroll
    for (int o = 16; o; o >>= 1) {
        ps += __shfl_xor_sync(0xffffffffu, ps, o);
        pd += __shfl_xor_sync(0xffffffffu, pd, o);
    }
    if (lane == 0) { g_as[warp] = ps; g_ad[warp] = pd; }
}

// ---------------- edge stage: warp per destination, single-pass online softmax ----------------
template <int F, bool WRITE_ALPHA>
__global__ void edge_kernel(int hbuf, const float* __restrict__ bias,
                            float* __restrict__ optr, int obuf,
                            float* __restrict__ alpha_out, int N, int do_relu) {
    const float* __restrict__ h = buf_ptr(hbuf);
    float* out = optr ? optr : buf_ptr(obuf);

    int warp = (blockIdx.x * blockDim.x + threadIdx.x) >> 5;
    int lane = threadIdx.x & 31;
    if (warp >= N) return;
    int n   = warp;
    int beg = g_offs[n], end = g_offs[n + 1];
    float adv = g_ad[n];

    float m = -1e30f, ssum = 0.f;
    float acc0 = 0.f, acc1 = 0.f;

    for (int c = beg; c < end; c += 32) {
        int j = c + lane;
        bool valid = (j < end);
        int s = valid ? g_csr_src[j] : 0;
        float e = valid ? (g_as[s] + adv) : -1e30f;
        e = (e > 0.f) ? e : 0.2f * e;

        // chunk max
        float cm = e;
        #pragma unroll
        for (int o = 16; o; o >>= 1) cm = fmaxf(cm, __shfl_xor_sync(0xffffffffu, cm, o));
        float nm = fmaxf(m, cm);
        float scale = __expf(m - nm);          // first chunk: exp(-1e30)≈0
        acc0 *= scale; acc1 *= scale; ssum *= scale;
        m = nm;

        float ex = __expf(e - nm);             // invalid lanes -> 0
        // chunk sum
        float cs = ex;
        #pragma unroll
        for (int o = 16; o; o >>= 1) cs += __shfl_xor_sync(0xffffffffu, cs, o);
        ssum += cs;

        // serial accumulate h with broadcast ex/s (independent gathers, high MLP)
        int cnt = end - c;
        if (cnt >= 32) {
            #pragma unroll 8
            for (int t = 0; t < 32; t++) {
                float ext = __shfl_sync(0xffffffffu, ex, t);
                int   st  = __shfl_sync(0xffffffffu, s, t);
                acc0 = fmaf(ext, h[st * F + lane], acc0);
                if (F == 64) acc1 = fmaf(ext, h[st * F + 32 + lane], acc1);
            }
        } else {
            for (int t = 0; t < cnt; t++) {
                float ext = __shfl_sync(0xffffffffu, ex, t);
                int   st  = __shfl_sync(0xffffffffu, s, t);
                acc0 = fmaf(ext, h[st * F + lane], acc0);
                if (F == 64) acc1 = fmaf(ext, h[st * F + 32 + lane], acc1);
            }
        }
    }
    float inv = 1.f / (ssum + 1e-16f);

    if (WRITE_ALPHA) {
        // lane-parallel alpha writeback (layer 1 only)
        for (int j = beg + lane; j < end; j += 32) {
            int s = g_csr_src[j];
            float e = g_as[s] + adv;
            e = (e > 0.f) ? e : 0.2f * e;
            alpha_out[g_csr_eid[j]] = __expf(e - m) * inv;
        }
    }

    float o0 = fmaf(acc0, inv, bias[lane]);
    if (do_relu) o0 = fmaxf(o0, 0.f);
    out[n * F + lane] = o0;
    if (F == 64) {
        float o1 = fmaf(acc1, inv, bias[32 + lane]);
        if (do_relu) o1 = fmaxf(o1, 0.f);
        out[n * F + 32 + lane] = o1;
    }
}

// ---------------- launch ----------------
extern "C" void kernel_launch(void* const* d_in, const int* in_sizes, int n_in,
                              void* d_out, int out_size) {
    const float* x  = (const float*)d_in[0];
    const int*   ei = (const int*)d_in[1];       // int32
    const float* W1 = (const float*)d_in[2];
    const float* as1 = (const float*)d_in[3];
    const float* ad1 = (const float*)d_in[4];
    const float* b1 = (const float*)d_in[5];
    const float* W2 = (const float*)d_in[6];
    const float* as2 = (const float*)d_in[7];
    const float* ad2 = (const float*)d_in[8];
    const float* b2 = (const float*)d_in[9];
    const float* W3 = (const float*)d_in[10];
    const float* as3 = (const float*)d_in[11];
    const float* ad3 = (const float*)d_in[12];
    const float* b3 = (const float*)d_in[13];

    int H1   = in_sizes[3];
    int FIN  = in_sizes[2] / H1;
    int N    = in_sizes[0] / FIN;
    int E    = in_sizes[1] / 2;
    int Etot = E + N;

    float* out = (float*)d_out;
    float* out_alpha = out + 2 * (size_t)Etot;
    float* out_feat  = out + 3 * (size_t)Etot;

    const int TB = 256;
    int ebl = (Etot + TB - 1) / TB;
    int nbl = (N + TB - 1) / TB;

    // ---- CSR build (shared by all 3 layers) ----
    zero_deg_kernel<<<nbl, TB>>>(N);
    deg_srcdst_kernel<<<ebl, TB>>>(ei, E, N, out);
    scan_kernel<<<1, 1024>>>(N);
    scatter_kernel<<<ebl, TB>>>(ei, E, N);

    int gemm_bl = (N + 127) / 128;
    int warp_bl = (N * 32 + TB - 1) / TB;  // warp-per-node kernels

    // buffer ids: 0=g_hA, 1=g_hB, 2=g_fA, 3=g_fB
    // ---- layer 1 ----
    gemm_kernel<128, 64><<<gemm_bl, 256>>>(x, -1, W1, 0, N);
    alpha_kernel<<<warp_bl, TB>>>(0, as1, ad1, N, 64);
    edge_kernel<64, true><<<warp_bl, TB>>>(0, b1, nullptr, 2, out_alpha, N, 1);

    // ---- layer 2 ----
    gemm_kernel<64, 64><<<gemm_bl, 256>>>(nullptr, 2, W2, 1, N);
    alpha_kernel<<<warp_bl, TB>>>(1, as2, ad2, N, 64);
    edge_kernel<64, false><<<warp_bl, TB>>>(1, b2, nullptr, 3, nullptr, N, 1);

    // ---- layer 3 ----
    gemm_kernel<64, 32><<<gemm_bl, 256>>>(nullptr, 3, W3, 0, N);
    alpha_kernel<<<warp_bl, TB>>>(0, as3, ad3, N, 32);
    edge_kernel<32, false><<<warp_bl, TB>>>(0, b3, out_feat, -1, nullptr, N, 0);

    (void)n_in; (void)out_size;
}